// round 13
// baseline (speedup 1.0000x reference)
#include <cuda_runtime.h>

// eTofts DCE-MRI forward model — round 11.
// Identical to round 10 (single kernel, 64 rows/CTA in 4 tile-iterations,
// amortized smem constant stage, width-16 segmented scan, __ldg cp loads,
// prefetched next-iter loads) EXCEPT: output stores use __stcs (evict-first).
// Rationale: cp (117MB) nearly fits L2 (~126MB) and is re-read every graph
// replay; plain .wb stores of out (117MB, write-once, never read) evict it.
// Evict-first stores minimize out's L2 footprint so cp stays resident.

#define TT 112

__device__ __forceinline__ float ex2f(float x) {
    float y;
    asm("ex2.approx.ftz.f32 %0, %1;" : "=f"(y) : "f"(x));
    return y;
}
__device__ __forceinline__ float rcpf(float x) {
    float y;
    asm("rcp.approx.ftz.f32 %0, %1;" : "=f"(y) : "f"(x));
    return y;
}

__global__ __launch_bounds__(256) void etofts_kernel(
    const float* __restrict__ param,
    const float* __restrict__ T10,
    const float* __restrict__ cp,
    float* __restrict__ out)
{
    __shared__ float  sraw[256];   // [0:192) param floats, [192:256) T10
    __shared__ float4 scst[64];    // {d, b_cp, b_u, c0} per CTA row

    const int tid  = threadIdx.x;
    const int lane = tid & 31;
    const int wrp  = tid >> 5;           // warp id in CTA (0..7)
    const int half = lane >> 4;          // which of the warp's 2 rows
    const int sl   = lane & 15;          // lane within 16-wide segment
    const bool active = sl < (TT / 8);   // 14 active lanes per segment

    const int rbase = blockIdx.x * 64;   // CTA's first row

    // ---- iter-0 cp loads FIRST: in flight under the whole prologue ----
    const int r0 = rbase + 2 * wrp + half;
    float4 va = make_float4(0.f, 0.f, 0.f, 0.f);
    float4 vb = make_float4(0.f, 0.f, 0.f, 0.f);
    if (active) {
        const float4* rp = (const float4*)(cp + (size_t)r0 * TT);
        va = __ldg(&rp[2 * sl]);
        vb = __ldg(&rp[2 * sl + 1]);
    }

    // ---- coalesced staging of param (48 float4) and T10 (16 float4) ----
    if (tid < 48) {
        const float4* p4 = (const float4*)(param + (size_t)rbase * 3);
        ((float4*)sraw)[tid] = __ldg(&p4[tid]);
    } else if (tid < 64) {
        const float4* t4 = (const float4*)(T10 + rbase);
        ((float4*)(sraw + 192))[tid - 48] = __ldg(&t4[tid - 48]);
    }
    __syncthreads();

    // ---- constants for all 64 CTA rows (threads 0..63) ----
    const float DELTT = 0.075f;                 // 4.5/60
    const float LOG2E = 1.4426950408889634f;
    const float TR    = 0.005f;
    const float SINA  = 0.25881904510252074f;   // sin(15 deg)
    const float COSA  = 0.9659258262890683f;    // cos(15 deg)
    const float numA  = 20.0f * SINA;

    if (tid < 64) {
        const float p0  = sraw[3 * tid + 0];    // stride 3: conflict-free
        const float p1  = sraw[3 * tid + 1];
        const float p2  = sraw[3 * tid + 2];
        const float t10 = sraw[192 + tid];

        const float ktrans = fminf(fmaxf(p0 * 0.2f, 1e-5f),   0.2f);
        const float vp     = fminf(fmaxf(p1 * 0.1f, 0.0005f), 0.1f);
        const float ve     = fminf(fmaxf(p2 * 0.6f, 0.04f),   0.6f);

        const float c1 = -(TR * 4.5f * LOG2E);
        float4 c;
        c.x = ex2f(-(ktrans * rcpf(ve)) * (DELTT * LOG2E));  // d
        c.y = c1 * vp;                                       // b_cp
        c.z = c1 * ktrans * DELTT;                           // b_u
        c.w = -(TR * LOG2E) * rcpf(t10);                     // c0
        scst[tid] = c;
    }
    __syncthreads();

    // ---- 4 tile-iterations, next-iter loads prefetched ----
    #pragma unroll 1
    for (int j = 0; j < 4; j++) {
        // prefetch next iter's cp (latency hidden under this iter's math)
        float4 nva = make_float4(0.f, 0.f, 0.f, 0.f);
        float4 nvb = make_float4(0.f, 0.f, 0.f, 0.f);
        if (j < 3 && active) {
            const int rn = rbase + 16 * (j + 1) + 2 * wrp + half;
            const float4* rp = (const float4*)(cp + (size_t)rn * TT);
            nva = __ldg(&rp[2 * sl]);
            nvb = __ldg(&rp[2 * sl + 1]);
        }

        const int lrow = 16 * j + 2 * wrp + half;   // row within CTA
        const float4 c = scst[lrow];                // broadcast LDS.128
        const float d    = c.x;
        const float b_cp = c.y;
        const float b_u  = c.z;
        const float c0   = c.w;

        // powers of d
        const float d2  = d   * d;
        const float d3  = d2  * d;
        const float d4  = d2  * d2;
        const float d8  = d4  * d4;
        const float d16 = d8  * d8;
        const float d32 = d16 * d16;
        const float d64 = d32 * d32;

        const float w1 = (sl >= 1) ? d8  : 0.0f;
        const float w2 = (sl >= 2) ? d16 : 0.0f;
        const float w4 = (sl >= 4) ? d32 : 0.0f;
        const float w8 = (sl >= 8) ? d64 : 0.0f;

        // local inclusive scan of 8 elements
        const float l0 = va.x;
        const float l1 = fmaf(d, l0, va.y);
        const float l2 = fmaf(d, l1, va.z);
        const float l3 = fmaf(d, l2, va.w);
        const float l4 = fmaf(d, l3, vb.x);
        const float l5 = fmaf(d, l4, vb.y);
        const float l6 = fmaf(d, l5, vb.z);
        const float l7 = fmaf(d, l6, vb.w);

        // width-16 segmented warp scan of end-states (factor d^8 per hop)
        float Bv = l7;
        float t;
        t = __shfl_up_sync(0xffffffffu, Bv, 1, 16); Bv = fmaf(t, w1, Bv);
        t = __shfl_up_sync(0xffffffffu, Bv, 2, 16); Bv = fmaf(t, w2, Bv);
        t = __shfl_up_sync(0xffffffffu, Bv, 4, 16); Bv = fmaf(t, w4, Bv);
        t = __shfl_up_sync(0xffffffffu, Bv, 8, 16); Bv = fmaf(t, w8, Bv);

        float U0 = __shfl_up_sync(0xffffffffu, Bv, 1, 16);
        if (sl == 0) U0 = 0.0f;

        // full IIR state per element
        const float u0 = fmaf(U0, d,  l0);
        const float u1 = fmaf(U0, d2, l1);
        const float u2 = fmaf(U0, d3, l2);
        const float u3 = fmaf(U0, d4, l3);
        const float u4 = fmaf(d, u3, vb.x);
        const float u5 = fmaf(d, u4, vb.y);
        const float u6 = fmaf(d, u5, vb.z);
        const float u7 = fmaf(d, u6, vb.w);

        // signal equation
        float4 ra, rb;
        {
            float E, num, den;
            E = ex2f(fmaf(b_cp, va.x, fmaf(b_u, u0, c0)));
            num = fmaf(E, -numA, numA); den = fmaf(E, -COSA, 1.0f); ra.x = num * rcpf(den);
            E = ex2f(fmaf(b_cp, va.y, fmaf(b_u, u1, c0)));
            num = fmaf(E, -numA, numA); den = fmaf(E, -COSA, 1.0f); ra.y = num * rcpf(den);
            E = ex2f(fmaf(b_cp, va.z, fmaf(b_u, u2, c0)));
            num = fmaf(E, -numA, numA); den = fmaf(E, -COSA, 1.0f); ra.z = num * rcpf(den);
            E = ex2f(fmaf(b_cp, va.w, fmaf(b_u, u3, c0)));
            num = fmaf(E, -numA, numA); den = fmaf(E, -COSA, 1.0f); ra.w = num * rcpf(den);
            E = ex2f(fmaf(b_cp, vb.x, fmaf(b_u, u4, c0)));
            num = fmaf(E, -numA, numA); den = fmaf(E, -COSA, 1.0f); rb.x = num * rcpf(den);
            E = ex2f(fmaf(b_cp, vb.y, fmaf(b_u, u5, c0)));
            num = fmaf(E, -numA, numA); den = fmaf(E, -COSA, 1.0f); rb.y = num * rcpf(den);
            E = ex2f(fmaf(b_cp, vb.z, fmaf(b_u, u6, c0)));
            num = fmaf(E, -numA, numA); den = fmaf(E, -COSA, 1.0f); rb.z = num * rcpf(den);
            E = ex2f(fmaf(b_cp, vb.w, fmaf(b_u, u7, c0)));
            num = fmaf(E, -numA, numA); den = fmaf(E, -COSA, 1.0f); rb.w = num * rcpf(den);
        }

        if (active) {
            const int rw = rbase + lrow;
            float4* outp = (float4*)(out + (size_t)rw * TT);
            __stcs(&outp[2 * sl],     ra);      // evict-first: keep cp in L2
            __stcs(&outp[2 * sl + 1], rb);
        }

        va = nva;
        vb = nvb;
    }
}

extern "C" void kernel_launch(void* const* d_in, const int* in_sizes, int n_in,
                              void* d_out, int out_size)
{
    const float* param = (const float*)d_in[0];
    const float* T10   = (const float*)d_in[1];
    const float* cp    = (const float*)d_in[2];
    float*       out   = (float*)d_out;

    const int B = in_sizes[1];          // T10 has B elements
    // 64 rows per 256-thread CTA
    etofts_kernel<<<B / 64, 256>>>(param, T10, cp, out);
}

// round 14
// speedup vs baseline: 1.0533x; 1.0533x over previous
#include <cuda_runtime.h>

// eTofts DCE-MRI forward model — round 12: VERBATIM reproduction of round 8
// (best scored result: 39.6us), to discriminate real structural advantage
// from run-to-run noise before building further on it.
// One kernel. CTA = 256 threads = 8 warps = 16 rows (2 rows per warp).
// Threads 0..15 compute per-row constants {d, b_cp, b_u, c0} into 256B smem;
// one barrier; each warp then reads its row's constants via broadcast LDS.128.
// Bulk cp loads (LDG.128, .cs) issued BEFORE the constant phase.

#define TT 112

__device__ __forceinline__ float ex2f(float x) {
    float y;
    asm("ex2.approx.ftz.f32 %0, %1;" : "=f"(y) : "f"(x));
    return y;
}
__device__ __forceinline__ float rcpf(float x) {
    float y;
    asm("rcp.approx.ftz.f32 %0, %1;" : "=f"(y) : "f"(x));
    return y;
}

__global__ __launch_bounds__(256) void etofts_kernel(
    const float* __restrict__ param,
    const float* __restrict__ T10,
    const float* __restrict__ cp,
    float* __restrict__ out)
{
    __shared__ float4 cst[16];           // {d, b_cp, b_u, c0} per CTA row

    const int tid  = threadIdx.x;
    const int lane = tid & 31;
    const int half = lane >> 4;          // which of the warp's 2 rows
    const int sl   = lane & 15;          // lane within 16-wide segment
    const bool active = sl < (TT / 8);   // 14 active lanes per segment

    const int rbase = blockIdx.x * 16;               // CTA's first row
    const int lrow  = (tid >> 5) * 2 + half;         // row index within CTA
    const int row   = rbase + lrow;

    // ---- bulk loads FIRST: LDG.128s in flight before constants/barrier ----
    const float4* rowp = (const float4*)(cp + (size_t)row * TT);
    float4 va = make_float4(0.f, 0.f, 0.f, 0.f);
    float4 vb = make_float4(0.f, 0.f, 0.f, 0.f);
    if (active) {
        va = __ldcs(&rowp[2 * sl]);
        vb = __ldcs(&rowp[2 * sl + 1]);
    }

    // ---- constant stage: threads 0..15 each handle one CTA row ----
    const float DELTT = 0.075f;                 // 4.5/60
    const float LOG2E = 1.4426950408889634f;
    const float TR    = 0.005f;
    const float SINA  = 0.25881904510252074f;   // sin(15 deg)
    const float COSA  = 0.9659258262890683f;    // cos(15 deg)
    const float numA  = 20.0f * SINA;

    if (tid < 16) {
        const int r = rbase + tid;
        const float p0  = __ldg(&param[3 * r + 0]);
        const float p1  = __ldg(&param[3 * r + 1]);
        const float p2  = __ldg(&param[3 * r + 2]);
        const float t10 = __ldg(&T10[r]);

        const float ktrans = fminf(fmaxf(p0 * 0.2f, 1e-5f),   0.2f);
        const float vp     = fminf(fmaxf(p1 * 0.1f, 0.0005f), 0.1f);
        const float ve     = fminf(fmaxf(p2 * 0.6f, 0.04f),   0.6f);

        const float c1 = -(TR * 4.5f * LOG2E);
        float4 c;
        c.x = ex2f(-(ktrans * rcpf(ve)) * (DELTT * LOG2E));  // d
        c.y = c1 * vp;                                       // b_cp
        c.z = c1 * ktrans * DELTT;                           // b_u
        c.w = -(TR * LOG2E) * rcpf(t10);                     // c0
        cst[tid] = c;
    }
    __syncthreads();

    // broadcast LDS.128: same address across each 16-lane segment
    const float4 c = cst[lrow];
    const float d    = c.x;
    const float b_cp = c.y;
    const float b_u  = c.z;
    const float c0   = c.w;

    // powers of d
    const float d2  = d   * d;
    const float d3  = d2  * d;
    const float d4  = d2  * d2;
    const float d8  = d4  * d4;
    const float d16 = d8  * d8;
    const float d32 = d16 * d16;
    const float d64 = d32 * d32;

    const float w1 = (sl >= 1) ? d8  : 0.0f;
    const float w2 = (sl >= 2) ? d16 : 0.0f;
    const float w4 = (sl >= 4) ? d32 : 0.0f;
    const float w8 = (sl >= 8) ? d64 : 0.0f;

    // local inclusive scan of 8 elements
    const float l0 = va.x;
    const float l1 = fmaf(d, l0, va.y);
    const float l2 = fmaf(d, l1, va.z);
    const float l3 = fmaf(d, l2, va.w);
    const float l4 = fmaf(d, l3, vb.x);
    const float l5 = fmaf(d, l4, vb.y);
    const float l6 = fmaf(d, l5, vb.z);
    const float l7 = fmaf(d, l6, vb.w);

    // width-16 segmented warp scan of end-states (factor d^8 per hop)
    float Bv = l7;
    float t;
    t = __shfl_up_sync(0xffffffffu, Bv, 1, 16); Bv = fmaf(t, w1, Bv);
    t = __shfl_up_sync(0xffffffffu, Bv, 2, 16); Bv = fmaf(t, w2, Bv);
    t = __shfl_up_sync(0xffffffffu, Bv, 4, 16); Bv = fmaf(t, w4, Bv);
    t = __shfl_up_sync(0xffffffffu, Bv, 8, 16); Bv = fmaf(t, w8, Bv);

    float U0 = __shfl_up_sync(0xffffffffu, Bv, 1, 16);  // state entering segment
    if (sl == 0) U0 = 0.0f;

    // full IIR state per element: first 4 via powers, last 4 via recurrence
    const float u0 = fmaf(U0, d,  l0);
    const float u1 = fmaf(U0, d2, l1);
    const float u2 = fmaf(U0, d3, l2);
    const float u3 = fmaf(U0, d4, l3);
    const float u4 = fmaf(d, u3, vb.x);
    const float u5 = fmaf(d, u4, vb.y);
    const float u6 = fmaf(d, u5, vb.z);
    const float u7 = fmaf(d, u6, vb.w);

    // signal equation
    float4 ra, rb;
    {
        float E, num, den;
        E = ex2f(fmaf(b_cp, va.x, fmaf(b_u, u0, c0)));
        num = fmaf(E, -numA, numA); den = fmaf(E, -COSA, 1.0f); ra.x = num * rcpf(den);
        E = ex2f(fmaf(b_cp, va.y, fmaf(b_u, u1, c0)));
        num = fmaf(E, -numA, numA); den = fmaf(E, -COSA, 1.0f); ra.y = num * rcpf(den);
        E = ex2f(fmaf(b_cp, va.z, fmaf(b_u, u2, c0)));
        num = fmaf(E, -numA, numA); den = fmaf(E, -COSA, 1.0f); ra.z = num * rcpf(den);
        E = ex2f(fmaf(b_cp, va.w, fmaf(b_u, u3, c0)));
        num = fmaf(E, -numA, numA); den = fmaf(E, -COSA, 1.0f); ra.w = num * rcpf(den);
        E = ex2f(fmaf(b_cp, vb.x, fmaf(b_u, u4, c0)));
        num = fmaf(E, -numA, numA); den = fmaf(E, -COSA, 1.0f); rb.x = num * rcpf(den);
        E = ex2f(fmaf(b_cp, vb.y, fmaf(b_u, u5, c0)));
        num = fmaf(E, -numA, numA); den = fmaf(E, -COSA, 1.0f); rb.y = num * rcpf(den);
        E = ex2f(fmaf(b_cp, vb.z, fmaf(b_u, u6, c0)));
        num = fmaf(E, -numA, numA); den = fmaf(E, -COSA, 1.0f); rb.z = num * rcpf(den);
        E = ex2f(fmaf(b_cp, vb.w, fmaf(b_u, u7, c0)));
        num = fmaf(E, -numA, numA); den = fmaf(E, -COSA, 1.0f); rb.w = num * rcpf(den);
    }

    // ---- coalesced streaming store ----
    if (active) {
        float4* outp = (float4*)(out + (size_t)row * TT);
        __stcs(&outp[2 * sl],     ra);
        __stcs(&outp[2 * sl + 1], rb);
    }
}

extern "C" void kernel_launch(void* const* d_in, const int* in_sizes, int n_in,
                              void* d_out, int out_size)
{
    const float* param = (const float*)d_in[0];
    const float* T10   = (const float*)d_in[1];
    const float* cp    = (const float*)d_in[2];
    float*       out   = (float*)d_out;

    const int B = in_sizes[1];          // T10 has B elements
    // 16 rows per 256-thread CTA
    etofts_kernel<<<B / 16, 256>>>(param, T10, cp, out);
}